// round 3
// baseline (speedup 1.0000x reference)
#include <cuda_runtime.h>
#include <math.h>

#define MARGIN 0.2f
#define EPS_V 1e-6f
#define MAXB 8192
#define NLAB 257   // labels in {-1, 0..255} -> index = label+1

// Scratch (device globals; no allocation allowed)
__device__ int   g_first[NLAB];
__device__ int   g_second[NLAB];
__device__ int   g_mfirst;
__device__ int   g_allsame;
__device__ float g_per[MAXB];
__device__ float g_valid[MAXB];

// ---------------------------------------------------------------------------
// K1: single block. Stage labels into SMEM once (vectorized), then all passes
// run out of SMEM: all_same flag, per-label first/second occurrence of the
// *effective* labels (with the all_same -1 overwrite for i<k), and mfirst.
// ---------------------------------------------------------------------------
__global__ void __launch_bounds__(1024) prep_kernel(const int* __restrict__ label,
                                                    int B, int k) {
    __shared__ int s_lab[MAXB];
    __shared__ int s_first[NLAB];
    __shared__ int s_second[NLAB];
    __shared__ int s_notsame;
    __shared__ int s_mfirst;

    const int tid = threadIdx.x;
    if (tid < NLAB) { s_first[tid] = 0x7fffffff; s_second[tid] = 0x7fffffff; }
    if (tid == 0)   { s_notsame = 0; s_mfirst = 0x7fffffff; }

    // Stage labels: vectorized int4 loads, high MLP (one pass over DRAM)
    const int nv = B >> 2;
    const int4* lab4 = (const int4*)label;
    for (int v = tid; v < nv; v += 1024)
        ((int4*)s_lab)[v] = lab4[v];
    for (int i = (nv << 2) + tid; i < B; i += 1024)   // tail (B not /4)
        s_lab[i] = label[i];
    __syncthreads();

    const int l0 = s_lab[0];
    for (int i = tid; i < B; i += 1024)
        if (s_lab[i] != l0) s_notsame = 1;   // benign race, write-only flag
    __syncthreads();

    const int allsame = !s_notsame;

    // first occurrence of each effective label
    for (int i = tid; i < B; i += 1024) {
        int eff = (allsame && i < k) ? -1 : s_lab[i];
        atomicMin(&s_first[eff + 1], i);
    }
    __syncthreads();

    // second occurrence + mfirst
    const int eff0 = allsame ? -1 : l0;   // k >= 2 so index 0 is overwritten
    for (int i = tid; i < B; i += 1024) {
        int eff = (allsame && i < k) ? -1 : s_lab[i];
        int li = eff + 1;
        if (i != s_first[li]) atomicMin(&s_second[li], i);
        if (eff != eff0)      atomicMin(&s_mfirst, i);
    }
    __syncthreads();

    if (tid < NLAB) { g_first[tid] = s_first[tid]; g_second[tid] = s_second[tid]; }
    if (tid == 0)   { g_mfirst = s_mfirst; g_allsame = allsame; }
}

// ---------------------------------------------------------------------------
// K2: one warp per row. a-row streamed with __ldcs (zero reuse; keep it out of
// the way of the reused pos/neg rows, which go through the default L1 path).
// Fully unrolled for C==1024 to front-batch ~24 LDG.128 per warp (max MLP).
// ---------------------------------------------------------------------------
__device__ __forceinline__ void acc_f4(float4 av, float4 pv, float4 nv,
                                       float& sap, float& san) {
    float d;
    d = av.x - pv.x + EPS_V; sap = fmaf(d, d, sap);
    d = av.y - pv.y + EPS_V; sap = fmaf(d, d, sap);
    d = av.z - pv.z + EPS_V; sap = fmaf(d, d, sap);
    d = av.w - pv.w + EPS_V; sap = fmaf(d, d, sap);
    d = av.x - nv.x + EPS_V; san = fmaf(d, d, san);
    d = av.y - nv.y + EPS_V; san = fmaf(d, d, san);
    d = av.z - nv.z + EPS_V; san = fmaf(d, d, san);
    d = av.w - nv.w + EPS_V; san = fmaf(d, d, san);
}

__global__ void __launch_bounds__(256) triplet_kernel(const float* __restrict__ z,
                                                      const int* __restrict__ label,
                                                      const int* __restrict__ zidx,
                                                      int B, int C, int k) {
    const int warp = threadIdx.x >> 5;
    const int lane = threadIdx.x & 31;
    const int i = blockIdx.x * 8 + warp;
    if (i >= B) return;

    const int allsame = g_allsame;
    const int eff_i = (allsame && i < k) ? -1 : label[i];
    const int li = eff_i + 1;

    const int f = g_first[li];                 // always <= i, valid index
    const int pos = (zidx[f] != zidx[i]) ? f : g_second[li];

    const int l0 = label[0];
    const int eff0 = allsame ? -1 : l0;
    const int neg = (eff_i != eff0) ? 0 : g_mfirst;

    const bool valid = (pos >= 0) && (pos < B) && (neg >= 0) && (neg < B);
    if (!valid) {
        if (lane == 0) { g_per[i] = 0.0f; g_valid[i] = 0.0f; }
        return;
    }

    const float4* a = (const float4*)(z + (size_t)i   * C);
    const float4* p = (const float4*)(z + (size_t)pos * C);
    const float4* n = (const float4*)(z + (size_t)neg * C);

    float sap = 0.0f, san = 0.0f;
    if (C == 1024) {
        // 256 float4 per row, lane-strided: exactly 8 iterations, fully unrolled
        #pragma unroll
        for (int u = 0; u < 8; u++) {
            const int v = lane + (u << 5);
            float4 av = __ldcs(&a[v]);   // streaming: evict-first
            float4 pv = __ldg(&p[v]);
            float4 nv = __ldg(&n[v]);
            acc_f4(av, pv, nv, sap, san);
        }
    } else {
        const int nvec = C >> 2;
        #pragma unroll 4
        for (int v = lane; v < nvec; v += 32) {
            float4 av = __ldcs(&a[v]);
            float4 pv = __ldg(&p[v]);
            float4 nv = __ldg(&n[v]);
            acc_f4(av, pv, nv, sap, san);
        }
    }
    #pragma unroll
    for (int o = 16; o > 0; o >>= 1) {
        sap += __shfl_xor_sync(0xffffffffu, sap, o);
        san += __shfl_xor_sync(0xffffffffu, san, o);
    }
    if (lane == 0) {
        float per = sqrtf(sap) - sqrtf(san) + MARGIN;
        g_per[i]   = fmaxf(per, 0.0f);
        g_valid[i] = 1.0f;
    }
}

// ---------------------------------------------------------------------------
// K3: deterministic single-block reduction -> scalar loss.
// ---------------------------------------------------------------------------
__global__ void __launch_bounds__(1024) finalize_kernel(float* __restrict__ out, int B) {
    __shared__ float s_s[1024];
    __shared__ float s_c[1024];
    const int tid = threadIdx.x;
    float s = 0.0f, c = 0.0f;
    for (int i = tid; i < B; i += 1024) { s += g_per[i]; c += g_valid[i]; }
    s_s[tid] = s; s_c[tid] = c;
    __syncthreads();
    #pragma unroll
    for (int o = 512; o > 0; o >>= 1) {
        if (tid < o) { s_s[tid] += s_s[tid + o]; s_c[tid] += s_c[tid + o]; }
        __syncthreads();
    }
    if (tid == 0) out[0] = (s_c[0] > 0.0f) ? (s_s[0] / s_c[0]) : 0.0f;
}

extern "C" void kernel_launch(void* const* d_in, const int* in_sizes, int n_in,
                              void* d_out, int out_size) {
    const int* z_label = (const int*)d_in[0];
    const int* z_idx   = (const int*)d_in[1];
    const float* z     = (const float*)d_in[2];
    float* out = (float*)d_out;

    const int B = in_sizes[0];
    const int C = in_sizes[2] / B;
    int k = (int)((double)B * 0.01);
    if (k < 2) k = 2;

    prep_kernel<<<1, 1024>>>(z_label, B, k);
    const int rows_per_block = 8;
    const int nblocks = (B + rows_per_block - 1) / rows_per_block;
    triplet_kernel<<<nblocks, 256>>>(z, z_label, z_idx, B, C, k);
    finalize_kernel<<<1, 1024>>>(out, B);
}

// round 4
// speedup vs baseline: 1.1199x; 1.1199x over previous
#include <cuda_runtime.h>
#include <math.h>

#define MARGIN 0.2f
#define EPS_V 1e-6f
#define MAXB 8192
#define NLAB 257   // labels in {-1, 0..255} -> index = label+1

// Scratch (device globals; no allocation allowed)
__device__ int   g_first[NLAB];
__device__ int   g_second[NLAB];
__device__ int   g_mfirst;
__device__ int   g_allsame;
__device__ float g_per[MAXB];
__device__ float g_valid[MAXB];

// ---------------------------------------------------------------------------
// K1: single block. Triggers PDL completion immediately (dependents may
// launch; they still wait on our results via cudaGridDependencySynchronize).
// Labels staged to SMEM; mfirst via warp ballot (1 atomic/warp, not 1/thread).
// ---------------------------------------------------------------------------
__global__ void __launch_bounds__(1024) prep_kernel(const int* __restrict__ label,
                                                    int B, int k) {
    cudaTriggerProgrammaticLaunchCompletion();

    __shared__ int s_lab[MAXB];
    __shared__ int s_first[NLAB];
    __shared__ int s_second[NLAB];
    __shared__ int s_notsame;
    __shared__ int s_mfirst;

    const int tid  = threadIdx.x;
    const int lane = tid & 31;
    if (tid < NLAB) { s_first[tid] = 0x7fffffff; s_second[tid] = 0x7fffffff; }
    if (tid == 0)   { s_notsame = 0; s_mfirst = 0x7fffffff; }

    // Stage labels (int4) + fold in the all-same check
    const int l0 = label[0];
    const int nv = B >> 2;
    const int4* lab4 = (const int4*)label;
    for (int v = tid; v < nv; v += 1024) {
        int4 t = lab4[v];
        ((int4*)s_lab)[v] = t;
        if (t.x != l0 || t.y != l0 || t.z != l0 || t.w != l0) s_notsame = 1;
    }
    for (int i = (nv << 2) + tid; i < B; i += 1024) {
        int t = label[i];
        s_lab[i] = t;
        if (t != l0) s_notsame = 1;
    }
    __syncthreads();

    const int allsame = !s_notsame;
    const int eff0 = allsame ? -1 : l0;   // k >= 2 so index 0 is overwritten

    // Pass 1: first occurrence per effective label; mfirst via ballot
    for (int i = tid; i < B; i += 1024) {
        int eff = (allsame && i < k) ? -1 : s_lab[i];
        atomicMin(&s_first[eff + 1], i);
        unsigned m = __ballot_sync(0xffffffffu, eff != eff0);
        if (lane == 0 && m) {
            int warp_base = i - lane;   // lanes have consecutive i
            atomicMin(&s_mfirst, warp_base + __ffs(m) - 1);
        }
    }
    __syncthreads();

    // Pass 2: second occurrence
    for (int i = tid; i < B; i += 1024) {
        int eff = (allsame && i < k) ? -1 : s_lab[i];
        int li = eff + 1;
        if (i != s_first[li]) atomicMin(&s_second[li], i);
    }
    __syncthreads();

    if (tid < NLAB) { g_first[tid] = s_first[tid]; g_second[tid] = s_second[tid]; }
    if (tid == 0)   { g_mfirst = s_mfirst; g_allsame = allsame; }
}

// ---------------------------------------------------------------------------
// K2: one warp per row. The a-row (the only DRAM-streaming operand) is loaded
// into an explicit float4[8] register array BEFORE the grid-dependency sync,
// forcing 8 back-to-back LDG.128 (high MLP) and overlapping with prep.
// pos/neg rows are few distinct rows -> L1/L2 resident.
// ---------------------------------------------------------------------------
__global__ void __launch_bounds__(256) triplet_kernel(const float* __restrict__ z,
                                                      const int* __restrict__ label,
                                                      const int* __restrict__ zidx,
                                                      int B, int C, int k) {
    const int warp = threadIdx.x >> 5;
    const int lane = threadIdx.x & 31;
    const int i = blockIdx.x * 8 + warp;

    // ---- independent of prep: start streaming the a-row immediately ----
    float4 av[8];
    const bool fast = (C == 1024) && (i < B);
    if (fast) {
        const float4* a = (const float4*)(z + (size_t)i * C);
        #pragma unroll
        for (int u = 0; u < 8; u++)
            av[u] = __ldcs(&a[lane + (u << 5)]);   // streaming: evict-first
    }
    const int lab_i = (i < B) ? label[i] : 0;
    const int l0    = label[0];
    const int idx_i = (i < B) ? zidx[i] : 0;

    // ---- wait for prep results ----
    cudaGridDependencySynchronize();
    if (i >= B) return;

    const int allsame = g_allsame;
    const int eff_i = (allsame && i < k) ? -1 : lab_i;
    const int li = eff_i + 1;

    const int f = g_first[li];                 // always <= i, valid index
    const int pos = (zidx[f] != idx_i) ? f : g_second[li];

    const int eff0 = allsame ? -1 : l0;
    const int neg = (eff_i != eff0) ? 0 : g_mfirst;

    const bool valid = (pos >= 0) && (pos < B) && (neg >= 0) && (neg < B);
    if (!valid) {
        if (lane == 0) { g_per[i] = 0.0f; g_valid[i] = 0.0f; }
        return;
    }

    const float4* p = (const float4*)(z + (size_t)pos * C);
    const float4* n = (const float4*)(z + (size_t)neg * C);

    float sap = 0.0f, san = 0.0f;
    if (fast) {
        #pragma unroll
        for (int u = 0; u < 8; u++) {
            const int v = lane + (u << 5);
            float4 pv = __ldg(&p[v]);
            float4 nv = __ldg(&n[v]);
            float d;
            d = av[u].x - pv.x + EPS_V; sap = fmaf(d, d, sap);
            d = av[u].y - pv.y + EPS_V; sap = fmaf(d, d, sap);
            d = av[u].z - pv.z + EPS_V; sap = fmaf(d, d, sap);
            d = av[u].w - pv.w + EPS_V; sap = fmaf(d, d, sap);
            d = av[u].x - nv.x + EPS_V; san = fmaf(d, d, san);
            d = av[u].y - nv.y + EPS_V; san = fmaf(d, d, san);
            d = av[u].z - nv.z + EPS_V; san = fmaf(d, d, san);
            d = av[u].w - nv.w + EPS_V; san = fmaf(d, d, san);
        }
    } else {
        const float4* a = (const float4*)(z + (size_t)i * C);
        const int nvec = C >> 2;
        for (int v = lane; v < nvec; v += 32) {
            float4 avv = __ldcs(&a[v]);
            float4 pv = __ldg(&p[v]);
            float4 nv = __ldg(&n[v]);
            float d;
            d = avv.x - pv.x + EPS_V; sap = fmaf(d, d, sap);
            d = avv.y - pv.y + EPS_V; sap = fmaf(d, d, sap);
            d = avv.z - pv.z + EPS_V; sap = fmaf(d, d, sap);
            d = avv.w - pv.w + EPS_V; sap = fmaf(d, d, sap);
            d = avv.x - nv.x + EPS_V; san = fmaf(d, d, san);
            d = avv.y - nv.y + EPS_V; san = fmaf(d, d, san);
            d = avv.z - nv.z + EPS_V; san = fmaf(d, d, san);
            d = avv.w - nv.w + EPS_V; san = fmaf(d, d, san);
        }
    }
    #pragma unroll
    for (int o = 16; o > 0; o >>= 1) {
        sap += __shfl_xor_sync(0xffffffffu, sap, o);
        san += __shfl_xor_sync(0xffffffffu, san, o);
    }
    if (lane == 0) {
        float per = sqrtf(sap) - sqrtf(san) + MARGIN;
        g_per[i]   = fmaxf(per, 0.0f);
        g_valid[i] = 1.0f;
    }
}

// ---------------------------------------------------------------------------
// K3: deterministic single-block reduction -> scalar loss.
// ---------------------------------------------------------------------------
__global__ void __launch_bounds__(1024) finalize_kernel(float* __restrict__ out, int B) {
    cudaGridDependencySynchronize();
    __shared__ float s_s[1024];
    __shared__ float s_c[1024];
    const int tid = threadIdx.x;
    float s = 0.0f, c = 0.0f;
    for (int i = tid; i < B; i += 1024) { s += g_per[i]; c += g_valid[i]; }
    s_s[tid] = s; s_c[tid] = c;
    __syncthreads();
    #pragma unroll
    for (int o = 512; o > 0; o >>= 1) {
        if (tid < o) { s_s[tid] += s_s[tid + o]; s_c[tid] += s_c[tid + o]; }
        __syncthreads();
    }
    if (tid == 0) out[0] = (s_c[0] > 0.0f) ? (s_s[0] / s_c[0]) : 0.0f;
}

extern "C" void kernel_launch(void* const* d_in, const int* in_sizes, int n_in,
                              void* d_out, int out_size) {
    const int* z_label = (const int*)d_in[0];
    const int* z_idx   = (const int*)d_in[1];
    const float* z     = (const float*)d_in[2];
    float* out = (float*)d_out;

    const int B = in_sizes[0];
    const int C = in_sizes[2] / B;
    int k = (int)((double)B * 0.01);
    if (k < 2) k = 2;

    prep_kernel<<<1, 1024>>>(z_label, B, k);

    // triplet: PDL — launches while prep runs; syncs internally
    {
        cudaLaunchConfig_t cfg = {};
        cfg.gridDim = dim3((B + 7) / 8);
        cfg.blockDim = dim3(256);
        cfg.dynamicSmemBytes = 0;
        cfg.stream = 0;
        cudaLaunchAttribute at[1];
        at[0].id = cudaLaunchAttributeProgrammaticStreamSerialization;
        at[0].val.programmaticStreamSerializationAllowed = 1;
        cfg.attrs = at;
        cfg.numAttrs = 1;
        cudaLaunchKernelEx(&cfg, triplet_kernel, z, z_label, z_idx, B, C, k);
    }

    // finalize: PDL — hides launch gap; syncs internally
    {
        cudaLaunchConfig_t cfg = {};
        cfg.gridDim = dim3(1);
        cfg.blockDim = dim3(1024);
        cfg.dynamicSmemBytes = 0;
        cfg.stream = 0;
        cudaLaunchAttribute at[1];
        at[0].id = cudaLaunchAttributeProgrammaticStreamSerialization;
        at[0].val.programmaticStreamSerializationAllowed = 1;
        cfg.attrs = at;
        cfg.numAttrs = 1;
        cudaLaunchKernelEx(&cfg, finalize_kernel, out, B);
    }
}